// round 16
// baseline (speedup 1.0000x reference)
#include <cuda_runtime.h>
#include <cuda_bf16.h>

#define N_BOND   100000
#define D        192
#define N_ETYPES 36
#define E_PER_T  30000
#define BATCH    256
#define N_EDGES  (N_ETYPES * E_PER_T)   // 1,080,000
#define N_SEG    (N_ETYPES * BATCH)     // 9216
#define N_OCT    (N_EDGES / 8)          // 135000

__device__ float g_s[N_BOND];     // per-node scalar projection h[i,:] . W_out
__device__ float g_acc[N_SEG];    // segment accumulators [type*BATCH + graph]

// ---- 256-bit evict_last loads (sm_103a requires v8.b32 / v4.b64 for the hint)
__device__ __forceinline__ void ldg_el_v8f(const float* p, float4& lo, float4& hi) {
    unsigned r0,r1,r2,r3,r4,r5,r6,r7;
    asm volatile("ld.global.L2::evict_last.v8.b32 {%0,%1,%2,%3,%4,%5,%6,%7}, [%8];"
                 : "=r"(r0),"=r"(r1),"=r"(r2),"=r"(r3),
                   "=r"(r4),"=r"(r5),"=r"(r6),"=r"(r7)
                 : "l"(p));
    lo.x=__uint_as_float(r0); lo.y=__uint_as_float(r1);
    lo.z=__uint_as_float(r2); lo.w=__uint_as_float(r3);
    hi.x=__uint_as_float(r4); hi.y=__uint_as_float(r5);
    hi.z=__uint_as_float(r6); hi.w=__uint_as_float(r7);
}
__device__ __forceinline__ void ldg_el_v4l(const void* p, int4& a, int4& b) {
    unsigned long long r0,r1,r2,r3;
    asm volatile("ld.global.L2::evict_last.v4.b64 {%0,%1,%2,%3}, [%4];"
                 : "=l"(r0),"=l"(r1),"=l"(r2),"=l"(r3) : "l"(p));
    a.x=(int)r0; a.y=(int)(r0>>32); a.z=(int)r1; a.w=(int)(r1>>32);
    b.x=(int)r2; b.y=(int)(r2>>32); b.z=(int)r3; b.w=(int)(r3>>32);
}
__device__ __forceinline__ float dot8(const float4& aLo, const float4& aHi,
                                      const float4& wLo, const float4& wHi) {
    return aLo.x*wLo.x + aLo.y*wLo.y + aLo.z*wLo.z + aLo.w*wLo.w
         + aHi.x*wHi.x + aHi.y*wHi.y + aHi.z*wHi.z + aHi.w*wHi.w;
}

// ---------------------------------------------------------------------------
// Kernel 1: s[row] = dot(h[row,:], W_out).  Half-warp per row, 4 rows/warp,
// 256-bit evict_last loads: lane hl loads row chunk hl (32B); lanes hl<8
// also load chunk 16+hl. W pre-split identically (16 regs/lane).
// Also zeroes g_acc; triggers PDL.
// ---------------------------------------------------------------------------
__global__ void dot_kernel(const float* __restrict__ h,
                           const float* __restrict__ W) {
    cudaTriggerProgrammaticLaunchCompletion();

    const int tid = blockIdx.x * blockDim.x + threadIdx.x;
    if (tid < N_SEG) g_acc[tid] = 0.f;

    const int lane = threadIdx.x & 31;
    const int half = lane >> 4;
    const int hl   = lane & 15;
    const int warp = tid >> 5;

    // W chunks: wa = W[8*hl .. 8*hl+7]; wb = W[128 + 8*hl ..] for hl<8.
    const float4* W4 = reinterpret_cast<const float4*>(W);
    const float4 waLo = W4[2*hl],      waHi = W4[2*hl + 1];
    float4 wbLo = make_float4(0,0,0,0), wbHi = make_float4(0,0,0,0);
    if (hl < 8) { wbLo = W4[32 + 2*hl]; wbHi = W4[32 + 2*hl + 1]; }

    const int row0 = 4 * warp + half;
    const int row1 = row0 + 2;
    if (row0 >= N_BOND) return;

    const float* p0 = h + (size_t)row0 * D;
    const float* p1 = h + (size_t)row1 * D;

    float4 a0Lo,a0Hi, a1Lo,a1Hi;
    ldg_el_v8f(p0 + 8*hl, a0Lo, a0Hi);
    ldg_el_v8f(p1 + 8*hl, a1Lo, a1Hi);
    float4 b0Lo,b0Hi, b1Lo,b1Hi;
    if (hl < 8) {
        ldg_el_v8f(p0 + 128 + 8*hl, b0Lo, b0Hi);
        ldg_el_v8f(p1 + 128 + 8*hl, b1Lo, b1Hi);
    }

    float acc0 = dot8(a0Lo, a0Hi, waLo, waHi);
    float acc1 = dot8(a1Lo, a1Hi, waLo, waHi);
    if (hl < 8) {
        acc0 += dot8(b0Lo, b0Hi, wbLo, wbHi);
        acc1 += dot8(b1Lo, b1Hi, wbLo, wbHi);
    }

    #pragma unroll
    for (int off = 8; off > 0; off >>= 1) {
        acc0 += __shfl_down_sync(0xffffffffu, acc0, off, 16);
        acc1 += __shfl_down_sync(0xffffffffu, acc1, off, 16);
    }
    if (hl == 0) {
        g_s[row0] = acc0;
        g_s[row1] = acc1;
    }
}

// ---------------------------------------------------------------------------
// Kernel 2: 8 edges per thread; src/seg via 32B v4.b64 evict_last loads in
// the PDL prologue; grid sync gates g_s gather / g_acc atomics.
// ---------------------------------------------------------------------------
__global__ void edge_kernel(const int* __restrict__ src,
                            const int* __restrict__ seg) {
    const int idx  = blockIdx.x * blockDim.x + threadIdx.x;
    const int lane = threadIdx.x & 31;

    int4 sA = {0,0,0,0}, sB = {0,0,0,0};
    int  k[8];
    bool active = (idx < N_OCT);

    if (active) {
        const int e0 = idx * 8;
        const int t  = e0 / E_PER_T;     // 8 | 30000: pack never crosses a type
        int4 gA, gB;
        ldg_el_v4l(reinterpret_cast<const int4*>(src) + idx * 2, sA, sB);
        ldg_el_v4l(reinterpret_cast<const int4*>(seg) + idx * 2, gA, gB);

        const int kb = t * BATCH;
        k[0] = kb + gA.x; k[1] = kb + gA.y; k[2] = kb + gA.z; k[3] = kb + gA.w;
        k[4] = kb + gB.x; k[5] = kb + gB.y; k[6] = kb + gB.z; k[7] = kb + gB.w;
    }

    cudaGridDependencySynchronize();     // dot done: g_s ready, g_acc zeroed

    float val = 0.f;
    int   key = -1;
    if (active) {
        float v[8];
        v[0] = g_s[sA.x]; v[1] = g_s[sA.y]; v[2] = g_s[sA.z]; v[3] = g_s[sA.w];
        v[4] = g_s[sB.x]; v[5] = g_s[sB.y]; v[6] = g_s[sB.z]; v[7] = g_s[sB.w];

        float acc = v[0]; int cur = k[0];
        #pragma unroll
        for (int j = 1; j < 8; j++) {
            if (k[j] == cur) acc += v[j];
            else { atomicAdd(&g_acc[cur], acc); cur = k[j]; acc = v[j]; }
        }
        val = acc; key = cur;
    }

    #pragma unroll
    for (int off = 1; off < 32; off <<= 1) {
        int   okey = __shfl_down_sync(0xffffffffu, key, off);
        float oval = __shfl_down_sync(0xffffffffu, val, off);
        if (lane + off < 32 && okey == key) val += oval;
    }
    int pkey = __shfl_up_sync(0xffffffffu, key, 1);
    if (((lane == 0) || (pkey != key)) && key >= 0) atomicAdd(&g_acc[key], val);
}

// ---------------------------------------------------------------------------
// Kernel 3: mask + softmax, warp-per-graph, shuffle-only. PDL mask prologue.
// ---------------------------------------------------------------------------
__global__ void softmax_kernel(const int* __restrict__ mask,
                               float* __restrict__ out) {
    const int lane = threadIdx.x & 31;
    const int wid  = threadIdx.x >> 5;              // 0..7
    const int b    = blockIdx.x * 8 + wid;          // graph id

    const int t0 = lane;                            // always < 36
    const int t1 = 32 + lane;                       // valid for lane < 4
    const int m0 = mask[b * N_ETYPES + t0];
    const int m1 = (lane < 4) ? mask[b * N_ETYPES + t1] : 1;

    cudaGridDependencySynchronize();                // g_acc final

    float x0 = g_acc[t0 * BATCH + b];
    float x1 = (lane < 4) ? g_acc[t1 * BATCH + b] : 0.f;
    if (m0 != 0) x0 = -1e9f;
    x1 = (lane < 4) ? ((m1 != 0) ? -1e9f : x1) : -3.402823466e38f;  // sentinel

    float mx = fmaxf(x0, x1);
    #pragma unroll
    for (int off = 16; off > 0; off >>= 1)
        mx = fmaxf(mx, __shfl_xor_sync(0xffffffffu, mx, off));

    float e0 = __expf(x0 - mx);
    float e1 = __expf(x1 - mx);                     // sentinel underflows to 0

    float s = e0 + e1;
    #pragma unroll
    for (int off = 16; off > 0; off >>= 1)
        s += __shfl_xor_sync(0xffffffffu, s, off);

    const float inv = 1.f / s;
    out[b * N_ETYPES + t0] = e0 * inv;
    if (lane < 4) out[b * N_ETYPES + t1] = e1 * inv;
}

// ---------------------------------------------------------------------------
static void launch_pdl(void* fn, dim3 grid, dim3 block, void** args) {
    cudaLaunchConfig_t cfg = {};
    cfg.gridDim  = grid;
    cfg.blockDim = block;
    cfg.stream   = 0;
    cudaLaunchAttribute attr[1];
    attr[0].id = cudaLaunchAttributeProgrammaticStreamSerialization;
    attr[0].val.programmaticStreamSerializationAllowed = 1;
    cfg.attrs = attr;
    cfg.numAttrs = 1;
    cudaLaunchKernelExC(&cfg, fn, args);
}

extern "C" void kernel_launch(void* const* d_in, const int* in_sizes, int n_in,
                              void* d_out, int out_size) {
    const float* h    = (const float*)d_in[0];   // [100000,192]
    const float* Wout = (const float*)d_in[1];   // [192,1]
    const int*   src  = (const int*)d_in[2];     // [36,30000]
    const int*   seg  = (const int*)d_in[3];     // [36,30000]
    const int*   mask = (const int*)d_in[4];     // [256,36] bool -> int32
    float*       out  = (float*)d_out;           // [256,36]

    dot_kernel<<<(N_BOND + 31) / 32, 256>>>(h, Wout);

    {
        void* args[] = { (void*)&src, (void*)&seg };
        launch_pdl((void*)edge_kernel, dim3((N_OCT + 255) / 256), dim3(256), args);
    }
    {
        void* args[] = { (void*)&mask, (void*)&out };
        launch_pdl((void*)softmax_kernel, dim3(BATCH / 8), dim3(256), args);
    }
}

// round 17
// speedup vs baseline: 1.0735x; 1.0735x over previous
#include <cuda_runtime.h>
#include <cuda_bf16.h>

#define N_BOND   100000
#define D        192
#define N_ETYPES 36
#define E_PER_T  30000
#define BATCH    256
#define N_EDGES  (N_ETYPES * E_PER_T)   // 1,080,000
#define N_SEG    (N_ETYPES * BATCH)     // 9216
#define N_OCT    (N_EDGES / 8)          // 135000

__device__ float g_s[N_BOND];     // per-node scalar projection h[i,:] . W_out
__device__ float g_acc[N_SEG];    // segment accumulators [type*BATCH + graph]

// ---------------------------------------------------------------------------
// Kernel 1: s[row] = dot(h[row,:], W_out).  Measured-best shape:
// half-warp per row, 4 rows per warp, 6 LDG.128 in flight, one-shot blocks
// (regs 34, occ ~66%, ~4.9-5.1 TB/s = this chip's effective DRAM ceiling).
// Also zeroes g_acc; triggers PDL for dependents.
// ---------------------------------------------------------------------------
__global__ void dot_kernel(const float* __restrict__ h,
                           const float* __restrict__ W) {
    cudaTriggerProgrammaticLaunchCompletion();

    const int tid = blockIdx.x * blockDim.x + threadIdx.x;
    if (tid < N_SEG) g_acc[tid] = 0.f;

    const int lane = threadIdx.x & 31;
    const int half = lane >> 4;
    const int hl   = lane & 15;
    const int warp = tid >> 5;

    const float4* W4 = reinterpret_cast<const float4*>(W);
    const float4 w0 = W4[hl];
    const float4 w1 = W4[16 + hl];
    const float4 w2 = W4[32 + hl];

    const int row0 = 4 * warp + half;
    const int row1 = row0 + 2;
    if (row0 >= N_BOND) return;

    const float4* p0 = reinterpret_cast<const float4*>(h + (size_t)row0 * D);
    const float4* p1 = reinterpret_cast<const float4*>(h + (size_t)row1 * D);
    float4 a0 = p0[hl], b0 = p0[16 + hl], c0 = p0[32 + hl];
    float4 a1 = p1[hl], b1 = p1[16 + hl], c1 = p1[32 + hl];

    float acc0 = a0.x * w0.x + a0.y * w0.y + a0.z * w0.z + a0.w * w0.w
               + b0.x * w1.x + b0.y * w1.y + b0.z * w1.z + b0.w * w1.w
               + c0.x * w2.x + c0.y * w2.y + c0.z * w2.z + c0.w * w2.w;
    float acc1 = a1.x * w0.x + a1.y * w0.y + a1.z * w0.z + a1.w * w0.w
               + b1.x * w1.x + b1.y * w1.y + b1.z * w1.z + b1.w * w1.w
               + c1.x * w2.x + c1.y * w2.y + c1.z * w2.z + c1.w * w2.w;

    #pragma unroll
    for (int off = 8; off > 0; off >>= 1) {
        acc0 += __shfl_down_sync(0xffffffffu, acc0, off, 16);
        acc1 += __shfl_down_sync(0xffffffffu, acc1, off, 16);
    }
    if (hl == 0) {
        g_s[row0] = acc0;
        g_s[row1] = acc1;
    }
}

// ---------------------------------------------------------------------------
// Kernel 2: 8 edges per thread; PDL prologue (index loads + key computation)
// overlaps dot's tail; grid sync gates g_s gather / g_acc atomics.
// ---------------------------------------------------------------------------
__global__ void edge_kernel(const int* __restrict__ src,
                            const int* __restrict__ seg) {
    const int idx  = blockIdx.x * blockDim.x + threadIdx.x;
    const int lane = threadIdx.x & 31;

    int4 sA = {0,0,0,0}, sB = {0,0,0,0};
    int  k[8];
    bool active = (idx < N_OCT);

    if (active) {
        const int e0 = idx * 8;
        const int t  = e0 / E_PER_T;     // 8 | 30000: pack never crosses a type
        const int4* s4p = reinterpret_cast<const int4*>(src) + idx * 2;
        const int4* g4p = reinterpret_cast<const int4*>(seg) + idx * 2;
        sA = s4p[0]; sB = s4p[1];
        int4 gA = g4p[0], gB = g4p[1];

        const int kb = t * BATCH;
        k[0] = kb + gA.x; k[1] = kb + gA.y; k[2] = kb + gA.z; k[3] = kb + gA.w;
        k[4] = kb + gB.x; k[5] = kb + gB.y; k[6] = kb + gB.z; k[7] = kb + gB.w;
    }

    cudaGridDependencySynchronize();     // dot done: g_s ready, g_acc zeroed

    float val = 0.f;
    int   key = -1;
    if (active) {
        float v[8];
        v[0] = g_s[sA.x]; v[1] = g_s[sA.y]; v[2] = g_s[sA.z]; v[3] = g_s[sA.w];
        v[4] = g_s[sB.x]; v[5] = g_s[sB.y]; v[6] = g_s[sB.z]; v[7] = g_s[sB.w];

        float acc = v[0]; int cur = k[0];
        #pragma unroll
        for (int j = 1; j < 8; j++) {
            if (k[j] == cur) acc += v[j];
            else { atomicAdd(&g_acc[cur], acc); cur = k[j]; acc = v[j]; }
        }
        val = acc; key = cur;
    }

    #pragma unroll
    for (int off = 1; off < 32; off <<= 1) {
        int   okey = __shfl_down_sync(0xffffffffu, key, off);
        float oval = __shfl_down_sync(0xffffffffu, val, off);
        if (lane + off < 32 && okey == key) val += oval;
    }
    int pkey = __shfl_up_sync(0xffffffffu, key, 1);
    if (((lane == 0) || (pkey != key)) && key >= 0) atomicAdd(&g_acc[key], val);
}

// ---------------------------------------------------------------------------
// Kernel 3: mask + softmax, warp-per-graph, shuffle-only (no smem, no
// __syncthreads). Lane covers t=lane; lanes 0-3 also t=32+lane.
// ---------------------------------------------------------------------------
__global__ void softmax_kernel(const int* __restrict__ mask,
                               float* __restrict__ out) {
    const int lane = threadIdx.x & 31;
    const int wid  = threadIdx.x >> 5;              // 0..7
    const int b    = blockIdx.x * 8 + wid;          // graph id

    const int t0 = lane;                            // always < 36
    const int t1 = 32 + lane;                       // valid for lane < 4
    const int m0 = mask[b * N_ETYPES + t0];
    const int m1 = (lane < 4) ? mask[b * N_ETYPES + t1] : 1;

    cudaGridDependencySynchronize();                // g_acc final

    float x0 = g_acc[t0 * BATCH + b];
    float x1 = (lane < 4) ? g_acc[t1 * BATCH + b] : 0.f;
    if (m0 != 0) x0 = -1e9f;
    x1 = (lane < 4) ? ((m1 != 0) ? -1e9f : x1) : -3.402823466e38f;  // sentinel

    float mx = fmaxf(x0, x1);
    #pragma unroll
    for (int off = 16; off > 0; off >>= 1)
        mx = fmaxf(mx, __shfl_xor_sync(0xffffffffu, mx, off));

    float e0 = __expf(x0 - mx);
    float e1 = __expf(x1 - mx);                     // sentinel underflows to 0

    float s = e0 + e1;
    #pragma unroll
    for (int off = 16; off > 0; off >>= 1)
        s += __shfl_xor_sync(0xffffffffu, s, off);

    const float inv = 1.f / s;
    out[b * N_ETYPES + t0] = e0 * inv;
    if (lane < 4) out[b * N_ETYPES + t1] = e1 * inv;
}

// ---------------------------------------------------------------------------
static void launch_pdl(void* fn, dim3 grid, dim3 block, void** args) {
    cudaLaunchConfig_t cfg = {};
    cfg.gridDim  = grid;
    cfg.blockDim = block;
    cfg.stream   = 0;
    cudaLaunchAttribute attr[1];
    attr[0].id = cudaLaunchAttributeProgrammaticStreamSerialization;
    attr[0].val.programmaticStreamSerializationAllowed = 1;
    cfg.attrs = attr;
    cfg.numAttrs = 1;
    cudaLaunchKernelExC(&cfg, fn, args);
}

extern "C" void kernel_launch(void* const* d_in, const int* in_sizes, int n_in,
                              void* d_out, int out_size) {
    const float* h    = (const float*)d_in[0];   // [100000,192]
    const float* Wout = (const float*)d_in[1];   // [192,1]
    const int*   src  = (const int*)d_in[2];     // [36,30000]
    const int*   seg  = (const int*)d_in[3];     // [36,30000]
    const int*   mask = (const int*)d_in[4];     // [256,36] bool -> int32
    float*       out  = (float*)d_out;           // [256,36]

    dot_kernel<<<(N_BOND + 31) / 32, 256>>>(h, Wout);

    {
        void* args[] = { (void*)&src, (void*)&seg };
        launch_pdl((void*)edge_kernel, dim3((N_OCT + 255) / 256), dim3(256), args);
    }
    {
        void* args[] = { (void*)&mask, (void*)&out };
        launch_pdl((void*)softmax_kernel, dim3(BATCH / 8), dim3(256), args);
    }
}